// round 10
// baseline (speedup 1.0000x reference)
#include <cuda_runtime.h>

#define PB   128
#define PHW  256
#define HW   1024
#define BIMG 8
#define NPER 16
#define NB   128
#define NGRP 4
#define NBG  (NB / NGRP)          // 32 boxes per gather group

#define THREADS    384
#define DS_BLOCKS  128            // 128*384 = 49152 = PB*PB*3
#define GT_BLOCKS  (NGRP * PB)    // 512
#define ROWS_PER_CP 16
#define CP_BLOCKS  (BIMG * HW / ROWS_PER_CP)   // 512
#define PS_BLOCKS  (NB * 4)       // 512: 4 blocks per box, 32 rows each
#define FN_BLOCKS  512            // 512*384 = 196608 = PHW*PHW*3
#define TOTAL_BLOCKS (DS_BLOCKS + GT_BLOCKS + CP_BLOCKS + PS_BLOCKS + FN_BLOCKS)

// Scratch (device globals — no allocation allowed)
__device__ float g_small[PB * PB * 3];              // downsampled patch
__device__ float g_smallT[PB * PB * 3];             // transposed copy (coalesced rot reads)
__device__ float g_nr[NGRP][PB][PB * 3];            // non-rot gather partials
__device__ float g_rt[NGRP][PB][PB * 3];            // rot gather partials (transposed)
__device__ int   g_sync[2];                          // [0]=ds done, [1]=gather done

// ---------------------------------------------------------------------------
// Role: antialiased bilinear downsample 256->128 (JAX triangle taps
// {0.25,0.75,0.75,0.25}, per-dim edge renormalization). Writes g_small + T.
// ---------------------------------------------------------------------------
__device__ void role_downsample(int bid, const float* __restrict__ patch) {
    int t = bid * THREADS + threadIdx.x;
    int c = t % 3;
    int j = (t / 3) % PB;
    int i = t / (3 * PB);

    const float w0[4] = {0.25f, 0.75f, 0.75f, 0.25f};
    int by = 2 * i - 1, bx = 2 * j - 1;
    float wy[4], wx[4], sy = 0.f, sx = 0.f;
#pragma unroll
    for (int u = 0; u < 4; u++) { int r = by + u; wy[u] = (r >= 0 && r < PHW) ? w0[u] : 0.f; sy += wy[u]; }
#pragma unroll
    for (int v = 0; v < 4; v++) { int q = bx + v; wx[v] = (q >= 0 && q < PHW) ? w0[v] : 0.f; sx += wx[v]; }

    float acc = 0.f;
#pragma unroll
    for (int u = 0; u < 4; u++) {
        if (wy[u] == 0.f) continue;
        int r = by + u;
        float rowacc = 0.f;
#pragma unroll
        for (int v = 0; v < 4; v++) {
            if (wx[v] == 0.f) continue;
            rowacc += wx[v] * __ldg(&patch[(r * PHW + (bx + v)) * 3 + c]);
        }
        acc += wy[u] * rowacc;
    }
    float val = acc / (sy * sx);
    g_small[t] = val;
    g_smallT[(j * PB + i) * 3 + c] = val;

    __syncthreads();
    __threadfence();
    if (threadIdx.x == 0) atomicAdd(&g_sync[0], 1);
}

// ---------------------------------------------------------------------------
// Role: gradient gather + inverse transform (coalesced for rot and non-rot).
// ---------------------------------------------------------------------------
__device__ void role_gather(int gb, const float* __restrict__ grads,
                            const int* __restrict__ box_yx,
                            const int* __restrict__ dec) {
    __shared__ int s_y[NBG], s_x[NBG], s_d[NBG], s_b[NBG];
    int tid = threadIdx.x;
    int g = gb >> 7;
    int r = gb & 127;

    if (tid < NBG) {
        int box = g * NBG + tid;
        s_y[tid] = __ldg(&box_yx[box * 2]);
        s_x[tid] = __ldg(&box_yx[box * 2 + 1]);
        s_d[tid] = (__ldg(&dec[box * 3]) > 0 ? 1 : 0) |
                   (__ldg(&dec[box * 3 + 1]) > 0 ? 2 : 0) |
                   (__ldg(&dec[box * 3 + 2]) > 0 ? 4 : 0);
        s_b[tid] = box >> 4;
    }
    __syncthreads();

    int j = tid / 3;
    int c = tid - 3 * j;

    float acc_nr = 0.f;
    float acc_rt = 0.f;
#pragma unroll 8
    for (int k = 0; k < NBG; ++k) {
        int d = s_d[k];
        size_t base = (size_t)s_b[k] * (HW * HW * 3);
        if (d & 1) {
            int row = s_y[k] + ((d & 4) ? r : (PB - 1 - r));
            int col = s_x[k] + ((d & 2) ? (PB - 1 - j) : j);
            acc_rt += __ldg(&grads[base + ((size_t)row * HW + col) * 3 + c]);
        } else {
            int row = s_y[k] + ((d & 4) ? (PB - 1 - r) : r);
            int col = s_x[k] + ((d & 2) ? (PB - 1 - j) : j);
            acc_nr += __ldg(&grads[base + ((size_t)row * HW + col) * 3 + c]);
        }
    }
    g_nr[g][r][tid] = acc_nr;
    g_rt[g][r][tid] = acc_rt;

    __syncthreads();
    __threadfence();
    if (tid == 0) atomicAdd(&g_sync[1], 1);
}

// ---------------------------------------------------------------------------
// Role: streaming copy, 16 rows/block, coverage-masked stores. Never waits.
// ---------------------------------------------------------------------------
__device__ void role_copy(int cb, const float* __restrict__ images,
                          const int* __restrict__ box_yx,
                          float* __restrict__ out) {
    int b = cb >> 6;                      // 64 blocks per image
    int ybase = (cb & 63) * ROWS_PER_CP;
    int tid = threadIdx.x;

    __shared__ unsigned s_cov[ROWS_PER_CP][32];   // 16 rows x 1024 bits

    // FIX R9: 512 words > 384 threads — must loop, not mask
    for (int w = tid; w < ROWS_PER_CP * 32; w += THREADS)
        ((unsigned*)s_cov)[w] = 0u;
    __syncthreads();

    // build coverage: 256 threads = (box, row)
    if (tid < NPER * ROWS_PER_CP) {
        int bx_ = tid >> 4;               // box 0..15
        int r = tid & 15;                 // row 0..15
        int boxid = b * NPER + bx_;
        int y0 = __ldg(&box_yx[boxid * 2]);
        if ((unsigned)(ybase + r - y0) < (unsigned)PB) {
            int x0 = __ldg(&box_yx[boxid * 2 + 1]);
            int w0 = x0 >> 5, off = x0 & 31;
            if (off == 0) {
#pragma unroll
                for (int w = 0; w < 4; w++) atomicOr(&s_cov[r][w0 + w], 0xFFFFFFFFu);
            } else {
                atomicOr(&s_cov[r][w0], 0xFFFFFFFFu << off);
#pragma unroll
                for (int w = 1; w < 4; w++) atomicOr(&s_cov[r][w0 + w], 0xFFFFFFFFu);
                atomicOr(&s_cov[r][w0 + 4], 0xFFFFFFFFu >> (32 - off));
            }
        }
    }
    __syncthreads();

    size_t base4 = ((size_t)(b * HW + ybase)) * (HW * 3 / 4);
    const float4* src4 = (const float4*)images + base4;
    float4* dst4 = (float4*)out + base4;

    // 16 rows x 768 float4/row; 384 threads -> 2 float4 per row per thread.
    // Process 2 rows per iteration = 4 float4 per thread (MLP=4, low regs).
#pragma unroll
    for (int rr = 0; rr < ROWS_PER_CP; rr += 2) {
        float4 v[4];
        int cc[4];
#pragma unroll
        for (int k = 0; k < 4; k++) {
            int row = rr + (k >> 1);
            int q = (k & 1) * THREADS + tid;          // float4 idx in row (0..767)
            int pa = (q * 4) / 3;                     // first pixel spanned
            int ca = (s_cov[row][pa >> 5] >> (pa & 31)) & 1;
            int cbit = (s_cov[row][(pa + 1) >> 5] >> ((pa + 1) & 31)) & 1;
            cc[k] = ca | (cbit << 1);
            if (cc[k] != 3)
                v[k] = src4[row * 768 + q];
        }
#pragma unroll
        for (int k = 0; k < 4; k++) {
            if (cc[k] == 3) continue;                 // fully pasted: paste blocks own it
            int row = rr + (k >> 1);
            int q = (k & 1) * THREADS + tid;
            float4* dp = &dst4[row * 768 + q];
            if (cc[k] == 0) {
                *dp = v[k];
            } else {
                int fo = q * 4;
                int pa = fo / 3;
                float* df = (float*)dp;
                const float* vf = (const float*)&v[k];
#pragma unroll
                for (int e = 0; e < 4; e++) {
                    int px = (fo + e) / 3;
                    int covered = (px == pa) ? (cc[k] & 1) : ((cc[k] >> 1) & 1);
                    if (!covered) df[e] = vf[e];
                }
            }
        }
    }
}

// ---------------------------------------------------------------------------
// Role: paste. 4 blocks per box, 32 rows each. Pure stores of the transformed
// tile; later-box-wins via a compacted overlap list (usually empty).
// ---------------------------------------------------------------------------
__device__ void role_paste(int pb_, const int* __restrict__ box_yx,
                           const int* __restrict__ dec,
                           float* __restrict__ out) {
    int box = pb_ >> 2;
    int rbase = (pb_ & 3) * 32;
    int b = box >> 4;
    int n = box & 15;
    int tid = threadIdx.x;

    __shared__ int s_y0, s_x0, s_d;
    __shared__ int l_y[NPER], l_x[NPER];
    __shared__ int l_cnt;

    if (tid == 0) {
        s_y0 = __ldg(&box_yx[box * 2]);
        s_x0 = __ldg(&box_yx[box * 2 + 1]);
        s_d = (__ldg(&dec[box * 3]) > 0 ? 1 : 0) |
              (__ldg(&dec[box * 3 + 1]) > 0 ? 2 : 0) |
              (__ldg(&dec[box * 3 + 2]) > 0 ? 4 : 0);
        l_cnt = 0;
    }
    __syncthreads();

    if (tid >= n + 1 && tid < NPER) {
        int mb = b * NPER + tid;
        int ym = __ldg(&box_yx[mb * 2]);
        int xm = __ldg(&box_yx[mb * 2 + 1]);
        int ylo = s_y0 + rbase, yhi = s_y0 + rbase + 32;
        bool ovl = (ym < yhi) && (ym + PB > ylo) &&
                   (xm < s_x0 + PB) && (xm + PB > s_x0);
        if (ovl) {
            int idx = atomicAdd(&l_cnt, 1);
            l_y[idx] = ym;
            l_x[idx] = xm;
        }
    }

    if (tid == 0) {
        volatile int* p = &g_sync[0];
        while (*p < DS_BLOCKS) __nanosleep(64);
    }
    __syncthreads();

    int rx = tid / 3;
    int c = tid - 3 * rx;
    int d = s_d;
    int x1 = (d & 2) ? (PB - 1 - rx) : rx;
    int xg = s_x0 + rx;
    int cnt = l_cnt;

    for (int r = 0; r < 32; r++) {
        int ry = rbase + r;
        int yg = s_y0 + ry;
        bool skip = false;
        for (int m = 0; m < cnt; m++) {
            if ((unsigned)(yg - l_y[m]) < (unsigned)PB &&
                (unsigned)(xg - l_x[m]) < (unsigned)PB) { skip = true; break; }
        }
        if (skip) continue;
        int y2 = (d & 4) ? (PB - 1 - ry) : ry;
        float val;
        if (d & 1) {
            int sx_ = PB - 1 - y2;
            val = g_smallT[(sx_ * PB + x1) * 3 + c];
        } else {
            val = g_small[(y2 * PB + x1) * 3 + c];
        }
        out[((size_t)(b * HW + yg) * HW + xg) * 3 + c] = val;
    }
}

// ---------------------------------------------------------------------------
// Role: reduce gather partials + bilinear upsample 128->256 + analytic TV grad.
// ---------------------------------------------------------------------------
__device__ __forceinline__ float acc_at(int y, int x, int c) {
    float s = 0.f;
#pragma unroll
    for (int g = 0; g < NGRP; g++) {
        s += g_nr[g][y][x * 3 + c];
        s += g_rt[g][x][y * 3 + c];
    }
    return s;
}

__device__ void role_final(int fb, const float* __restrict__ patch,
                           float* __restrict__ agg) {
    if (threadIdx.x == 0) {
        volatile int* p = &g_sync[1];
        while (*p < GT_BLOCKS) __nanosleep(64);
    }
    __syncthreads();

    int t = fb * THREADS + threadIdx.x;
    int c = t % 3;
    int j = (t / 3) % PHW;
    int i = t / (PHW * 3);

    int ky = i >> 1, y0, y1; float wy0, wy1;
    if (i & 1) { y0 = ky;             y1 = min(ky + 1, PB - 1); wy0 = 0.75f; wy1 = 0.25f; }
    else       { y0 = max(ky - 1, 0); y1 = ky;                  wy0 = 0.25f; wy1 = 0.75f; }
    int kx = j >> 1, x0, x1; float wx0, wx1;
    if (j & 1) { x0 = kx;             x1 = min(kx + 1, PB - 1); wx0 = 0.75f; wx1 = 0.25f; }
    else       { x0 = max(kx - 1, 0); x1 = kx;                  wx0 = 0.25f; wx1 = 0.75f; }

    float v = wy0 * (wx0 * acc_at(y0, x0, c) + wx1 * acc_at(y0, x1, c))
            + wy1 * (wx0 * acc_at(y1, x0, c) + wx1 * acc_at(y1, x1, c));

    float pij = __ldg(&patch[(i * PHW + j) * 3 + c]);
    float a = (j < PHW - 1) ? (pij - __ldg(&patch[(i * PHW + j + 1) * 3 + c])) : 0.f;
    float bb = (i < PHW - 1) ? (pij - __ldg(&patch[((i + 1) * PHW + j) * 3 + c])) : 0.f;
    float g = (a + bb) * rsqrtf(a * a + bb * bb + 1e-12f);
    if (j > 0) {
        float pl = __ldg(&patch[(i * PHW + j - 1) * 3 + c]);
        float al = pl - pij;
        float bl = (i < PHW - 1) ? (pl - __ldg(&patch[((i + 1) * PHW + j - 1) * 3 + c])) : 0.f;
        g -= al * rsqrtf(al * al + bl * bl + 1e-12f);
    }
    if (i > 0) {
        float pu = __ldg(&patch[((i - 1) * PHW + j) * 3 + c]);
        float bu = pu - pij;
        float au = (j < PHW - 1) ? (pu - __ldg(&patch[((i - 1) * PHW + j + 1) * 3 + c])) : 0.f;
        g -= bu * rsqrtf(au * au + bu * bu + 1e-12f);
    }
    agg[t] = v + 0.5f * g;
}

// ---------------------------------------------------------------------------
__global__ void __launch_bounds__(THREADS, 4) k_mega(
        const float* __restrict__ images, const float* __restrict__ grads,
        const float* __restrict__ patch,
        const int* __restrict__ box_yx, const int* __restrict__ dec,
        float* __restrict__ out, float* __restrict__ agg) {
    int bid = blockIdx.x;
    if (bid < DS_BLOCKS) {
        role_downsample(bid, patch);
    } else if (bid < DS_BLOCKS + GT_BLOCKS) {
        role_gather(bid - DS_BLOCKS, grads, box_yx, dec);
    } else if (bid < DS_BLOCKS + GT_BLOCKS + CP_BLOCKS) {
        role_copy(bid - (DS_BLOCKS + GT_BLOCKS), images, box_yx, out);
    } else if (bid < DS_BLOCKS + GT_BLOCKS + CP_BLOCKS + PS_BLOCKS) {
        role_paste(bid - (DS_BLOCKS + GT_BLOCKS + CP_BLOCKS), box_yx, dec, out);
    } else {
        role_final(bid - (DS_BLOCKS + GT_BLOCKS + CP_BLOCKS + PS_BLOCKS), patch, agg);
    }
}

// ---------------------------------------------------------------------------
extern "C" void kernel_launch(void* const* d_in, const int* in_sizes, int n_in,
                              void* d_out, int out_size) {
    const float* images = (const float*)d_in[0];
    const float* grads  = (const float*)d_in[1];
    const float* patch  = (const float*)d_in[2];
    const int*   box_yx = (const int*)d_in[3];
    const int*   dec    = (const int*)d_in[4];

    float* out = (float*)d_out;
    size_t img_elems = (size_t)BIMG * HW * HW * 3;
    float* agg = out + img_elems;

    void* sptr = nullptr;
    cudaGetSymbolAddress(&sptr, g_sync);
    cudaMemsetAsync(sptr, 0, 2 * sizeof(int));

    k_mega<<<TOTAL_BLOCKS, THREADS>>>(images, grads, patch, box_yx, dec, out, agg);
}

// round 12
// speedup vs baseline: 1.0114x; 1.0114x over previous
#include <cuda_runtime.h>
#include <cstdint>

#define PB   128
#define PHW  256
#define HW   1024
#define BIMG 8
#define NPER 16
#define NB   128
#define NGRP 4
#define NBG  (NB / NGRP)          // 32 boxes per gather group

#define THREADS    384
#define DS_BLOCKS  128            // 128*384 = 49152 = PB*PB*3
#define GT_BLOCKS  (NGRP * PB)    // 512
#define ROWS_PER_CP 2
#define CP_BLOCKS  (BIMG * HW / ROWS_PER_CP)   // 4096
#define FN_BLOCKS  512            // 512*384 = 196608 = PHW*PHW*3
#define TOTAL_BLOCKS (DS_BLOCKS + GT_BLOCKS + CP_BLOCKS + FN_BLOCKS)

#define CHUNK_BYTES (ROWS_PER_CP * HW * 3 * 4)    // 24576
#define SMEM_BYTES  (CHUNK_BYTES + 256)           // + mbar + box info

// Scratch (device globals — no allocation allowed)
__device__ float g_small[PB * PB * 3];              // downsampled patch
__device__ float g_smallT[PB * PB * 3];             // transposed copy
__device__ float g_nr[NGRP][PB][PB * 3];            // non-rot gather partials
__device__ float g_rt[NGRP][PB][PB * 3];            // rot gather partials (transposed)
__device__ int   g_sync[2];                          // [0]=ds done, [1]=gather done

// ---------------------------------------------------------------------------
__device__ __forceinline__ uint32_t smem_u32(const void* p) {
    uint32_t a;
    asm("{ .reg .u64 t; cvta.to.shared.u64 t, %1; cvt.u32.u64 %0, t; }" : "=r"(a) : "l"(p));
    return a;
}
__device__ __forceinline__ void mbar_init(uint32_t mbar, uint32_t cnt) {
    asm volatile("mbarrier.init.shared.b64 [%0], %1;" :: "r"(mbar), "r"(cnt) : "memory");
}
__device__ __forceinline__ void mbar_expect(uint32_t mbar, uint32_t bytes) {
    asm volatile("mbarrier.arrive.expect_tx.shared.b64 _, [%0], %1;" :: "r"(mbar), "r"(bytes) : "memory");
}
__device__ __forceinline__ void mbar_wait(uint32_t mbar, uint32_t parity) {
    uint32_t done;
    asm volatile(
        "{\n\t.reg .pred p;\n\t"
        "mbarrier.try_wait.parity.acquire.cta.shared::cta.b64 p, [%1], %2;\n\t"
        "selp.b32 %0, 1, 0, p;\n\t}"
        : "=r"(done) : "r"(mbar), "r"(parity) : "memory");
    if (!done) {
        asm volatile(
            "{\n\t.reg .pred P1;\n\t"
            "WL_%=:\n\t"
            "mbarrier.try_wait.parity.acquire.cta.shared::cta.b64 P1, [%0], %1, 0x989680;\n\t"
            "@P1 bra.uni WD_%=;\n\t"
            "bra.uni WL_%=;\n\t"
            "WD_%=:\n\t}"
            :: "r"(mbar), "r"(parity) : "memory");
    }
}
__device__ __forceinline__ void bulk_g2s(uint32_t dst_s, const void* src_g, uint32_t bytes, uint32_t mbar) {
    asm volatile("cp.async.bulk.shared::cta.global.mbarrier::complete_tx::bytes [%0], [%1], %2, [%3];"
                 :: "r"(dst_s), "l"(src_g), "r"(bytes), "r"(mbar) : "memory");
}
__device__ __forceinline__ void bulk_s2g(void* dst_g, uint32_t src_s, uint32_t bytes) {
    asm volatile("cp.async.bulk.global.shared::cta.bulk_group [%0], [%1], %2;"
                 :: "l"(dst_g), "r"(src_s), "r"(bytes) : "memory");
    asm volatile("cp.async.bulk.commit_group;" ::: "memory");
    asm volatile("cp.async.bulk.wait_group.read 0;" ::: "memory");
}

// ---------------------------------------------------------------------------
// Role: antialiased bilinear downsample 256->128 (JAX triangle taps
// {0.25,0.75,0.75,0.25}, per-dim edge renormalization). Writes g_small + T.
// ---------------------------------------------------------------------------
__device__ void role_downsample(int bid, const float* __restrict__ patch) {
    int t = bid * THREADS + threadIdx.x;
    int c = t % 3;
    int j = (t / 3) % PB;
    int i = t / (3 * PB);

    const float w0[4] = {0.25f, 0.75f, 0.75f, 0.25f};
    int by = 2 * i - 1, bx = 2 * j - 1;
    float wy[4], wx[4], sy = 0.f, sx = 0.f;
#pragma unroll
    for (int u = 0; u < 4; u++) { int r = by + u; wy[u] = (r >= 0 && r < PHW) ? w0[u] : 0.f; sy += wy[u]; }
#pragma unroll
    for (int v = 0; v < 4; v++) { int q = bx + v; wx[v] = (q >= 0 && q < PHW) ? w0[v] : 0.f; sx += wx[v]; }

    float acc = 0.f;
#pragma unroll
    for (int u = 0; u < 4; u++) {
        if (wy[u] == 0.f) continue;
        int r = by + u;
        float rowacc = 0.f;
#pragma unroll
        for (int v = 0; v < 4; v++) {
            if (wx[v] == 0.f) continue;
            rowacc += wx[v] * __ldg(&patch[(r * PHW + (bx + v)) * 3 + c]);
        }
        acc += wy[u] * rowacc;
    }
    float val = acc / (sy * sx);
    g_small[t] = val;
    g_smallT[(j * PB + i) * 3 + c] = val;

    __syncthreads();
    __threadfence();
    if (threadIdx.x == 0) atomicAdd(&g_sync[0], 1);
}

// ---------------------------------------------------------------------------
// Role: gradient gather + inverse transform (coalesced for rot and non-rot).
// ---------------------------------------------------------------------------
__device__ void role_gather(int gb, const float* __restrict__ grads,
                            const int* __restrict__ box_yx,
                            const int* __restrict__ dec, char* smem) {
    int* s_y = (int*)smem;
    int* s_x = s_y + NBG;
    int* s_d = s_x + NBG;
    int* s_b = s_d + NBG;
    int tid = threadIdx.x;
    int g = gb >> 7;
    int r = gb & 127;

    if (tid < NBG) {
        int box = g * NBG + tid;
        s_y[tid] = __ldg(&box_yx[box * 2]);
        s_x[tid] = __ldg(&box_yx[box * 2 + 1]);
        s_d[tid] = (__ldg(&dec[box * 3]) > 0 ? 1 : 0) |
                   (__ldg(&dec[box * 3 + 1]) > 0 ? 2 : 0) |
                   (__ldg(&dec[box * 3 + 2]) > 0 ? 4 : 0);
        s_b[tid] = box >> 4;
    }
    __syncthreads();

    int j = tid / 3;
    int c = tid - 3 * j;

    float acc_nr = 0.f;
    float acc_rt = 0.f;
#pragma unroll 8
    for (int k = 0; k < NBG; ++k) {
        int d = s_d[k];
        size_t base = (size_t)s_b[k] * (HW * HW * 3);
        if (d & 1) {
            int row = s_y[k] + ((d & 4) ? r : (PB - 1 - r));
            int col = s_x[k] + ((d & 2) ? (PB - 1 - j) : j);
            acc_rt += __ldg(&grads[base + ((size_t)row * HW + col) * 3 + c]);
        } else {
            int row = s_y[k] + ((d & 4) ? (PB - 1 - r) : r);
            int col = s_x[k] + ((d & 2) ? (PB - 1 - j) : j);
            acc_nr += __ldg(&grads[base + ((size_t)row * HW + col) * 3 + c]);
        }
    }
    g_nr[g][r][tid] = acc_nr;
    g_rt[g][r][tid] = acc_rt;

    __syncthreads();
    __threadfence();
    if (tid == 0) atomicAdd(&g_sync[1], 1);
}

// ---------------------------------------------------------------------------
// Role: TMA bulk copy + in-SMEM paste compositing. 2 rows per block.
// Bulk-load 24KB -> composite covered pixels in smem -> bulk-store 24KB.
// Later-box-wins needs a barrier between box iterations: the overwriting
// thread for box n+1 differs from box n's thread at the same pixel.
// ---------------------------------------------------------------------------
__device__ void role_copy(int cb, const float* __restrict__ images,
                          const int* __restrict__ box_yx, const int* __restrict__ dec,
                          float* __restrict__ out, char* smem) {
    int b = cb >> 9;                          // 512 blocks per image
    int ybase = (cb & 511) * ROWS_PER_CP;
    int tid = threadIdx.x;

    float* buf = (float*)smem;
    uint32_t buf_s = smem_u32(smem);
    uint32_t mbar = buf_s + CHUNK_BYTES;
    int* s_y0 = (int*)(smem + CHUNK_BYTES + 8);
    int* s_x0 = s_y0 + NPER;
    int* s_d  = s_x0 + NPER;
    int* s_rows = s_d + NPER;                 // bitmask of covered rows

    const float* srcf = images + (size_t)(b * HW + ybase) * (HW * 3);
    float*       dstf = out    + (size_t)(b * HW + ybase) * (HW * 3);

    if (tid == 0) { mbar_init(mbar, 1); s_rows[0] = 0; }
    __syncthreads();
    if (tid == 0) {
        mbar_expect(mbar, CHUNK_BYTES);
        bulk_g2s(buf_s, srcf, CHUNK_BYTES, mbar);
    }
    // box metadata while the bulk load is in flight
    if (tid < NPER) {
        int box = b * NPER + tid;
        int y0 = __ldg(&box_yx[box * 2]);
        s_y0[tid] = y0;
        s_x0[tid] = __ldg(&box_yx[box * 2 + 1]);
        s_d[tid]  = (__ldg(&dec[box * 3]) > 0 ? 1 : 0) |
                    (__ldg(&dec[box * 3 + 1]) > 0 ? 2 : 0) |
                    (__ldg(&dec[box * 3 + 2]) > 0 ? 4 : 0);
        int m = 0;
#pragma unroll
        for (int r = 0; r < ROWS_PER_CP; r++)
            if ((unsigned)(ybase + r - y0) < (unsigned)PB) m |= 1 << r;
        if (m) atomicOr(s_rows, m);
    }
    __syncthreads();
    int rowsmask = s_rows[0];

    if (rowsmask) {                            // need the downsampled patch
        if (tid == 0) {
            volatile int* p = &g_sync[0];
            while (*p < DS_BLOCKS) __nanosleep(64);
        }
        __syncthreads();
    }

    mbar_wait(mbar, 0);                        // smem tile resident

    if (rowsmask) {
        int rx = tid / 3;
        int c = tid - 3 * rx;
        for (int n = 0; n < NPER; n++) {       // ascending: later box must win
#pragma unroll
            for (int r = 0; r < ROWS_PER_CP; r++) {
                if (!((rowsmask >> r) & 1)) continue;
                int yg = ybase + r;
                int ry = yg - s_y0[n];
                if ((unsigned)ry >= (unsigned)PB) continue;
                int d = s_d[n];
                int y2 = (d & 4) ? (PB - 1 - ry) : ry;
                int x1 = (d & 2) ? (PB - 1 - rx) : rx;
                float val;
                if (d & 1) {
                    int sx_ = PB - 1 - y2;
                    val = g_smallT[(sx_ * PB + x1) * 3 + c];
                } else {
                    val = g_small[(y2 * PB + x1) * 3 + c];
                }
                buf[r * (HW * 3) + s_x0[n] * 3 + tid] = val;
            }
            // order box n's writes before box n+1's (different threads may
            // target the same pixel when boxes overlap)
            __syncthreads();
        }
    }
    __syncthreads();
    asm volatile("fence.proxy.async.shared::cta;" ::: "memory");
    if (tid == 0) bulk_s2g(dstf, buf_s, CHUNK_BYTES);
}

// ---------------------------------------------------------------------------
// Role: reduce gather partials + bilinear upsample 128->256 + analytic TV grad.
// ---------------------------------------------------------------------------
__device__ __forceinline__ float acc_at(int y, int x, int c) {
    float s = 0.f;
#pragma unroll
    for (int g = 0; g < NGRP; g++) {
        s += g_nr[g][y][x * 3 + c];
        s += g_rt[g][x][y * 3 + c];
    }
    return s;
}

__device__ void role_final(int fb, const float* __restrict__ patch,
                           float* __restrict__ agg) {
    if (threadIdx.x == 0) {
        volatile int* p = &g_sync[1];
        while (*p < GT_BLOCKS) __nanosleep(64);
    }
    __syncthreads();

    int t = fb * THREADS + threadIdx.x;
    int c = t % 3;
    int j = (t / 3) % PHW;
    int i = t / (PHW * 3);

    int ky = i >> 1, y0, y1; float wy0, wy1;
    if (i & 1) { y0 = ky;             y1 = min(ky + 1, PB - 1); wy0 = 0.75f; wy1 = 0.25f; }
    else       { y0 = max(ky - 1, 0); y1 = ky;                  wy0 = 0.25f; wy1 = 0.75f; }
    int kx = j >> 1, x0, x1; float wx0, wx1;
    if (j & 1) { x0 = kx;             x1 = min(kx + 1, PB - 1); wx0 = 0.75f; wx1 = 0.25f; }
    else       { x0 = max(kx - 1, 0); x1 = kx;                  wx0 = 0.25f; wx1 = 0.75f; }

    float v = wy0 * (wx0 * acc_at(y0, x0, c) + wx1 * acc_at(y0, x1, c))
            + wy1 * (wx0 * acc_at(y1, x0, c) + wx1 * acc_at(y1, x1, c));

    float pij = __ldg(&patch[(i * PHW + j) * 3 + c]);
    float a = (j < PHW - 1) ? (pij - __ldg(&patch[(i * PHW + j + 1) * 3 + c])) : 0.f;
    float bb = (i < PHW - 1) ? (pij - __ldg(&patch[((i + 1) * PHW + j) * 3 + c])) : 0.f;
    float g = (a + bb) * rsqrtf(a * a + bb * bb + 1e-12f);
    if (j > 0) {
        float pl = __ldg(&patch[(i * PHW + j - 1) * 3 + c]);
        float al = pl - pij;
        float bl = (i < PHW - 1) ? (pl - __ldg(&patch[((i + 1) * PHW + j - 1) * 3 + c])) : 0.f;
        g -= al * rsqrtf(al * al + bl * bl + 1e-12f);
    }
    if (i > 0) {
        float pu = __ldg(&patch[((i - 1) * PHW + j) * 3 + c]);
        float bu = pu - pij;
        float au = (j < PHW - 1) ? (pu - __ldg(&patch[((i - 1) * PHW + j + 1) * 3 + c])) : 0.f;
        g -= bu * rsqrtf(au * au + bu * bu + 1e-12f);
    }
    agg[t] = v + 0.5f * g;
}

// ---------------------------------------------------------------------------
__global__ void __launch_bounds__(THREADS, 4) k_mega(
        const float* __restrict__ images, const float* __restrict__ grads,
        const float* __restrict__ patch,
        const int* __restrict__ box_yx, const int* __restrict__ dec,
        float* __restrict__ out, float* __restrict__ agg) {
    __shared__ __align__(128) char s_mem[SMEM_BYTES];
    int bid = blockIdx.x;
    if (bid < DS_BLOCKS) {
        role_downsample(bid, patch);
    } else if (bid < DS_BLOCKS + GT_BLOCKS) {
        role_gather(bid - DS_BLOCKS, grads, box_yx, dec, s_mem);
    } else if (bid < DS_BLOCKS + GT_BLOCKS + CP_BLOCKS) {
        role_copy(bid - (DS_BLOCKS + GT_BLOCKS), images, box_yx, dec, out, s_mem);
    } else {
        role_final(bid - (DS_BLOCKS + GT_BLOCKS + CP_BLOCKS), patch, agg);
    }
}

// ---------------------------------------------------------------------------
extern "C" void kernel_launch(void* const* d_in, const int* in_sizes, int n_in,
                              void* d_out, int out_size) {
    const float* images = (const float*)d_in[0];
    const float* grads  = (const float*)d_in[1];
    const float* patch  = (const float*)d_in[2];
    const int*   box_yx = (const int*)d_in[3];
    const int*   dec    = (const int*)d_in[4];

    float* out = (float*)d_out;
    size_t img_elems = (size_t)BIMG * HW * HW * 3;
    float* agg = out + img_elems;

    void* sptr = nullptr;
    cudaGetSymbolAddress(&sptr, g_sync);
    cudaMemsetAsync(sptr, 0, 2 * sizeof(int));

    k_mega<<<TOTAL_BLOCKS, THREADS>>>(images, grads, patch, box_yx, dec, out, agg);
}

// round 13
// speedup vs baseline: 1.0746x; 1.0624x over previous
#include <cuda_runtime.h>

#define PB   128
#define PHW  256
#define HW   1024
#define BIMG 8
#define NPER 16
#define NB   128
#define NGRP 4
#define NBG  (NB / NGRP)          // 32 boxes per gather group

#define THREADS    384
#define DS_BLOCKS  128            // 128*384 = 49152 = PB*PB*3
#define GT_BLOCKS  (NGRP * PB)    // 512
#define ROWS_PER_CP 4
#define CP_BLOCKS  (BIMG * HW / ROWS_PER_CP)   // 2048
#define CP_HALF    (CP_BLOCKS / 2)             // 1024
#define PS_BLOCKS  (NB * 4)       // 512: 4 blocks per box, 32 rows each
#define FN_BLOCKS  512            // 512*384 = 196608 = PHW*PHW*3
#define TOTAL_BLOCKS (DS_BLOCKS + GT_BLOCKS + CP_BLOCKS + PS_BLOCKS + FN_BLOCKS)

// Role boundaries (bid ranges). Final sits MID-copy so its work overlaps the
// remaining copy instead of forming a serial tail; by its schedule time the
// gather is long done (gather bids all precede final bids -> no deadlock).
#define B_DS0   0
#define B_GT0   (B_DS0 + DS_BLOCKS)               // 128
#define B_CP0A  (B_GT0 + GT_BLOCKS)               // 640   copy[0:1024)
#define B_FN0   (B_CP0A + CP_HALF)                // 1664  final
#define B_CP0B  (B_FN0 + FN_BLOCKS)               // 2176  copy[1024:2048)
#define B_PS0   (B_CP0B + CP_HALF)                // 3200  paste
// total = 3712

// Scratch (device globals — no allocation allowed)
__device__ float g_small[PB * PB * 3];              // downsampled patch
__device__ float g_smallT[PB * PB * 3];             // transposed copy (coalesced rot reads)
__device__ float g_nr[NGRP][PB][PB * 3];            // non-rot gather partials
__device__ float g_rt[NGRP][PB][PB * 3];            // rot gather partials (transposed)
__device__ int   g_sync[2];                          // [0]=ds done, [1]=gather done

// ---------------------------------------------------------------------------
// Role: antialiased bilinear downsample 256->128 (JAX triangle taps
// {0.25,0.75,0.75,0.25}, per-dim edge renormalization). Writes g_small + T.
// ---------------------------------------------------------------------------
__device__ void role_downsample(int bid, const float* __restrict__ patch) {
    int t = bid * THREADS + threadIdx.x;
    int c = t % 3;
    int j = (t / 3) % PB;
    int i = t / (3 * PB);

    const float w0[4] = {0.25f, 0.75f, 0.75f, 0.25f};
    int by = 2 * i - 1, bx = 2 * j - 1;
    float wy[4], wx[4], sy = 0.f, sx = 0.f;
#pragma unroll
    for (int u = 0; u < 4; u++) { int r = by + u; wy[u] = (r >= 0 && r < PHW) ? w0[u] : 0.f; sy += wy[u]; }
#pragma unroll
    for (int v = 0; v < 4; v++) { int q = bx + v; wx[v] = (q >= 0 && q < PHW) ? w0[v] : 0.f; sx += wx[v]; }

    float acc = 0.f;
#pragma unroll
    for (int u = 0; u < 4; u++) {
        if (wy[u] == 0.f) continue;
        int r = by + u;
        float rowacc = 0.f;
#pragma unroll
        for (int v = 0; v < 4; v++) {
            if (wx[v] == 0.f) continue;
            rowacc += wx[v] * __ldg(&patch[(r * PHW + (bx + v)) * 3 + c]);
        }
        acc += wy[u] * rowacc;
    }
    float val = acc / (sy * sx);
    g_small[t] = val;
    g_smallT[(j * PB + i) * 3 + c] = val;

    __syncthreads();
    __threadfence();
    if (threadIdx.x == 0) atomicAdd(&g_sync[0], 1);
}

// ---------------------------------------------------------------------------
// Role: gradient gather + inverse transform (coalesced for rot and non-rot).
// ---------------------------------------------------------------------------
__device__ void role_gather(int gb, const float* __restrict__ grads,
                            const int* __restrict__ box_yx,
                            const int* __restrict__ dec) {
    __shared__ int s_y[NBG], s_x[NBG], s_d[NBG], s_b[NBG];
    int tid = threadIdx.x;
    int g = gb >> 7;
    int r = gb & 127;

    if (tid < NBG) {
        int box = g * NBG + tid;
        s_y[tid] = __ldg(&box_yx[box * 2]);
        s_x[tid] = __ldg(&box_yx[box * 2 + 1]);
        s_d[tid] = (__ldg(&dec[box * 3]) > 0 ? 1 : 0) |
                   (__ldg(&dec[box * 3 + 1]) > 0 ? 2 : 0) |
                   (__ldg(&dec[box * 3 + 2]) > 0 ? 4 : 0);
        s_b[tid] = box >> 4;
    }
    __syncthreads();

    int j = tid / 3;
    int c = tid - 3 * j;

    float acc_nr = 0.f;
    float acc_rt = 0.f;
#pragma unroll 8
    for (int k = 0; k < NBG; ++k) {
        int d = s_d[k];
        size_t base = (size_t)s_b[k] * (HW * HW * 3);
        if (d & 1) {
            int row = s_y[k] + ((d & 4) ? r : (PB - 1 - r));
            int col = s_x[k] + ((d & 2) ? (PB - 1 - j) : j);
            acc_rt += __ldg(&grads[base + ((size_t)row * HW + col) * 3 + c]);
        } else {
            int row = s_y[k] + ((d & 4) ? (PB - 1 - r) : r);
            int col = s_x[k] + ((d & 2) ? (PB - 1 - j) : j);
            acc_nr += __ldg(&grads[base + ((size_t)row * HW + col) * 3 + c]);
        }
    }
    g_nr[g][r][tid] = acc_nr;
    g_rt[g][r][tid] = acc_rt;

    __syncthreads();
    __threadfence();
    if (tid == 0) atomicAdd(&g_sync[1], 1);
}

// ---------------------------------------------------------------------------
// Role: streaming copy, 4 rows/block, coverage-masked stores. Never waits.
// Fully-covered quads skip both the read and the write (paste blocks own them).
// ---------------------------------------------------------------------------
__device__ void role_copy(int cb, const float* __restrict__ images,
                          const int* __restrict__ box_yx,
                          float* __restrict__ out) {
    int b = cb >> 8;                     // 256 blocks per image
    int ybase = (cb & 255) * ROWS_PER_CP;
    int tid = threadIdx.x;

    __shared__ unsigned s_cov[ROWS_PER_CP][32];   // 4 rows x 1024 bits

    for (int w = tid; w < ROWS_PER_CP * 32; w += THREADS)
        ((unsigned*)s_cov)[w] = 0u;
    __syncthreads();

    // build coverage: 64 threads = (box, row)
    if (tid < NPER * ROWS_PER_CP) {
        int bx_ = tid >> 2;              // box 0..15
        int r = tid & 3;                 // row 0..3
        int boxid = b * NPER + bx_;
        int y0 = __ldg(&box_yx[boxid * 2]);
        if ((unsigned)(ybase + r - y0) < (unsigned)PB) {
            int x0 = __ldg(&box_yx[boxid * 2 + 1]);
            int w0 = x0 >> 5, off = x0 & 31;
            if (off == 0) {
#pragma unroll
                for (int w = 0; w < 4; w++) atomicOr(&s_cov[r][w0 + w], 0xFFFFFFFFu);
            } else {
                atomicOr(&s_cov[r][w0], 0xFFFFFFFFu << off);
#pragma unroll
                for (int w = 1; w < 4; w++) atomicOr(&s_cov[r][w0 + w], 0xFFFFFFFFu);
                atomicOr(&s_cov[r][w0 + 4], 0xFFFFFFFFu >> (32 - off));
            }
        }
    }
    __syncthreads();

    size_t base4 = ((size_t)(b * HW + ybase)) * (HW * 3 / 4);
    const float4* src4 = (const float4*)images + base4;
    float4* dst4 = (float4*)out + base4;

#pragma unroll
    for (int h = 0; h < 2; h++) {
        float4 v[4];
        int cc[4];
#pragma unroll
        for (int k = 0; k < 4; k++) {
            int q = h * 4 + k;
            int row = q >> 1;
            int qq = (q & 1) * THREADS + tid;         // float4 idx in row
            int pa = (qq * 4) / 3;                    // first pixel spanned
            int ca = (s_cov[row][pa >> 5] >> (pa & 31)) & 1;
            int cbit = (s_cov[row][(pa + 1) >> 5] >> ((pa + 1) & 31)) & 1;
            cc[k] = ca | (cbit << 1);
            if (cc[k] != 3)
                v[k] = __ldcs(&src4[row * 768 + qq]);
        }
#pragma unroll
        for (int k = 0; k < 4; k++) {
            if (cc[k] == 3) continue;                 // fully pasted
            int q = h * 4 + k;
            int row = q >> 1;
            int qq = (q & 1) * THREADS + tid;
            float4* dp = &dst4[row * 768 + qq];
            if (cc[k] == 0) {
                __stcs(dp, v[k]);
            } else {
                int fo = qq * 4;
                int pa = fo / 3;
                float* df = (float*)dp;
                const float* vf = (const float*)&v[k];
#pragma unroll
                for (int e = 0; e < 4; e++) {
                    int px = (fo + e) / 3;
                    int covered = (px == pa) ? (cc[k] & 1) : ((cc[k] >> 1) & 1);
                    if (!covered) df[e] = vf[e];
                }
            }
        }
    }
}

// ---------------------------------------------------------------------------
// Role: paste. 4 blocks per box, 32 rows each. Pure stores of the transformed
// tile; later-box-wins via a compacted overlap list (usually empty).
// ---------------------------------------------------------------------------
__device__ void role_paste(int pb_, const int* __restrict__ box_yx,
                           const int* __restrict__ dec,
                           float* __restrict__ out) {
    int box = pb_ >> 2;
    int rbase = (pb_ & 3) * 32;
    int b = box >> 4;
    int n = box & 15;
    int tid = threadIdx.x;

    __shared__ int s_y0, s_x0, s_d;
    __shared__ int l_y[NPER], l_x[NPER];
    __shared__ int l_cnt;

    if (tid == 0) {
        s_y0 = __ldg(&box_yx[box * 2]);
        s_x0 = __ldg(&box_yx[box * 2 + 1]);
        s_d = (__ldg(&dec[box * 3]) > 0 ? 1 : 0) |
              (__ldg(&dec[box * 3 + 1]) > 0 ? 2 : 0) |
              (__ldg(&dec[box * 3 + 2]) > 0 ? 4 : 0);
        l_cnt = 0;
    }
    __syncthreads();

    if (tid >= n + 1 && tid < NPER) {
        int mb = b * NPER + tid;
        int ym = __ldg(&box_yx[mb * 2]);
        int xm = __ldg(&box_yx[mb * 2 + 1]);
        int ylo = s_y0 + rbase, yhi = s_y0 + rbase + 32;
        bool ovl = (ym < yhi) && (ym + PB > ylo) &&
                   (xm < s_x0 + PB) && (xm + PB > s_x0);
        if (ovl) {
            int idx = atomicAdd(&l_cnt, 1);
            l_y[idx] = ym;
            l_x[idx] = xm;
        }
    }

    if (tid == 0) {
        volatile int* p = &g_sync[0];
        while (*p < DS_BLOCKS) __nanosleep(64);
    }
    __syncthreads();

    int rx = tid / 3;
    int c = tid - 3 * rx;
    int d = s_d;
    int x1 = (d & 2) ? (PB - 1 - rx) : rx;
    int xg = s_x0 + rx;
    int cnt = l_cnt;

    for (int r = 0; r < 32; r++) {
        int ry = rbase + r;
        int yg = s_y0 + ry;
        bool skip = false;
        for (int m = 0; m < cnt; m++) {
            if ((unsigned)(yg - l_y[m]) < (unsigned)PB &&
                (unsigned)(xg - l_x[m]) < (unsigned)PB) { skip = true; break; }
        }
        if (skip) continue;
        int y2 = (d & 4) ? (PB - 1 - ry) : ry;
        float val;
        if (d & 1) {
            int sx_ = PB - 1 - y2;
            val = g_smallT[(sx_ * PB + x1) * 3 + c];
        } else {
            val = g_small[(y2 * PB + x1) * 3 + c];
        }
        out[((size_t)(b * HW + yg) * HW + xg) * 3 + c] = val;
    }
}

// ---------------------------------------------------------------------------
// Role: reduce gather partials + bilinear upsample 128->256 + analytic TV grad.
// ---------------------------------------------------------------------------
__device__ __forceinline__ float acc_at(int y, int x, int c) {
    float s = 0.f;
#pragma unroll
    for (int g = 0; g < NGRP; g++) {
        s += g_nr[g][y][x * 3 + c];
        s += g_rt[g][x][y * 3 + c];
    }
    return s;
}

__device__ void role_final(int fb, const float* __restrict__ patch,
                           float* __restrict__ agg) {
    if (threadIdx.x == 0) {
        volatile int* p = &g_sync[1];
        while (*p < GT_BLOCKS) __nanosleep(64);
    }
    __syncthreads();

    int t = fb * THREADS + threadIdx.x;
    int c = t % 3;
    int j = (t / 3) % PHW;
    int i = t / (PHW * 3);

    int ky = i >> 1, y0, y1; float wy0, wy1;
    if (i & 1) { y0 = ky;             y1 = min(ky + 1, PB - 1); wy0 = 0.75f; wy1 = 0.25f; }
    else       { y0 = max(ky - 1, 0); y1 = ky;                  wy0 = 0.25f; wy1 = 0.75f; }
    int kx = j >> 1, x0, x1; float wx0, wx1;
    if (j & 1) { x0 = kx;             x1 = min(kx + 1, PB - 1); wx0 = 0.75f; wx1 = 0.25f; }
    else       { x0 = max(kx - 1, 0); x1 = kx;                  wx0 = 0.25f; wx1 = 0.75f; }

    float v = wy0 * (wx0 * acc_at(y0, x0, c) + wx1 * acc_at(y0, x1, c))
            + wy1 * (wx0 * acc_at(y1, x0, c) + wx1 * acc_at(y1, x1, c));

    float pij = __ldg(&patch[(i * PHW + j) * 3 + c]);
    float a = (j < PHW - 1) ? (pij - __ldg(&patch[(i * PHW + j + 1) * 3 + c])) : 0.f;
    float bb = (i < PHW - 1) ? (pij - __ldg(&patch[((i + 1) * PHW + j) * 3 + c])) : 0.f;
    float g = (a + bb) * rsqrtf(a * a + bb * bb + 1e-12f);
    if (j > 0) {
        float pl = __ldg(&patch[(i * PHW + j - 1) * 3 + c]);
        float al = pl - pij;
        float bl = (i < PHW - 1) ? (pl - __ldg(&patch[((i + 1) * PHW + j - 1) * 3 + c])) : 0.f;
        g -= al * rsqrtf(al * al + bl * bl + 1e-12f);
    }
    if (i > 0) {
        float pu = __ldg(&patch[((i - 1) * PHW + j) * 3 + c]);
        float bu = pu - pij;
        float au = (j < PHW - 1) ? (pu - __ldg(&patch[((i - 1) * PHW + j + 1) * 3 + c])) : 0.f;
        g -= bu * rsqrtf(au * au + bu * bu + 1e-12f);
    }
    agg[t] = v + 0.5f * g;
}

// ---------------------------------------------------------------------------
// Mega kernel. Bid layout: ds | gather | copy[0:1024) | final | copy[1024:) |
// paste — final overlaps the copy's second half instead of tailing the kernel.
// ---------------------------------------------------------------------------
__global__ void __launch_bounds__(THREADS, 4) k_mega(
        const float* __restrict__ images, const float* __restrict__ grads,
        const float* __restrict__ patch,
        const int* __restrict__ box_yx, const int* __restrict__ dec,
        float* __restrict__ out, float* __restrict__ agg) {
    int bid = blockIdx.x;
    if (bid < B_GT0) {
        role_downsample(bid, patch);
    } else if (bid < B_CP0A) {
        role_gather(bid - B_GT0, grads, box_yx, dec);
    } else if (bid < B_FN0) {
        role_copy(bid - B_CP0A, images, box_yx, out);          // copy 0..1023
    } else if (bid < B_CP0B) {
        role_final(bid - B_FN0, patch, agg);
    } else if (bid < B_PS0) {
        role_copy(CP_HALF + (bid - B_CP0B), images, box_yx, out);  // copy 1024..2047
    } else {
        role_paste(bid - B_PS0, box_yx, dec, out);
    }
}

// ---------------------------------------------------------------------------
extern "C" void kernel_launch(void* const* d_in, const int* in_sizes, int n_in,
                              void* d_out, int out_size) {
    const float* images = (const float*)d_in[0];
    const float* grads  = (const float*)d_in[1];
    const float* patch  = (const float*)d_in[2];
    const int*   box_yx = (const int*)d_in[3];
    const int*   dec    = (const int*)d_in[4];

    float* out = (float*)d_out;
    size_t img_elems = (size_t)BIMG * HW * HW * 3;
    float* agg = out + img_elems;

    void* sptr = nullptr;
    cudaGetSymbolAddress(&sptr, g_sync);
    cudaMemsetAsync(sptr, 0, 2 * sizeof(int));

    k_mega<<<TOTAL_BLOCKS, THREADS>>>(images, grads, patch, box_yx, dec, out, agg);
}

// round 14
// speedup vs baseline: 1.2032x; 1.1197x over previous
#include <cuda_runtime.h>

#define PB   128
#define PHW  256
#define HW   1024
#define BIMG 8
#define NPER 16
#define NB   128
#define NGRP 4
#define NBG  (NB / NGRP)          // 32 boxes per gather group

#define THREADS    384
#define DS_BLOCKS  128            // 128*384 = 49152 = PB*PB*3
#define GT_BLOCKS  (NGRP * PB)    // 512
#define PS_BLOCKS  (NB * 4)       // 512: 4 blocks per box, 32 rows each
#define ROWS_PER_CP 4
#define CP_BLOCKS  (BIMG * HW / ROWS_PER_CP)   // 2048
#define FN_BLOCKS  512            // 512*384 = 196608 = PHW*PHW*3
#define TOTAL_BLOCKS (DS_BLOCKS + GT_BLOCKS + PS_BLOCKS + CP_BLOCKS + FN_BLOCKS)

// Scratch (device globals — no allocation allowed)
__device__ float g_small[PB * PB * 3];              // downsampled patch
__device__ float g_smallT[PB * PB * 3];             // transposed copy (coalesced rot reads)
__device__ float g_nr[NGRP][PB][PB * 3];            // non-rot gather partials
__device__ float g_rt[NGRP][PB][PB * 3];            // rot gather partials (transposed)
__device__ int   g_sync[2];                          // [0]=ds done, [1]=gather done

// ---------------------------------------------------------------------------
// Role: antialiased bilinear downsample 256->128 (JAX triangle taps
// {0.25,0.75,0.75,0.25}, per-dim edge renormalization). Writes g_small + T.
// ---------------------------------------------------------------------------
__device__ void role_downsample(int bid, const float* __restrict__ patch) {
    int t = bid * THREADS + threadIdx.x;
    int c = t % 3;
    int j = (t / 3) % PB;
    int i = t / (3 * PB);

    const float w0[4] = {0.25f, 0.75f, 0.75f, 0.25f};
    int by = 2 * i - 1, bx = 2 * j - 1;
    float wy[4], wx[4], sy = 0.f, sx = 0.f;
#pragma unroll
    for (int u = 0; u < 4; u++) { int r = by + u; wy[u] = (r >= 0 && r < PHW) ? w0[u] : 0.f; sy += wy[u]; }
#pragma unroll
    for (int v = 0; v < 4; v++) { int q = bx + v; wx[v] = (q >= 0 && q < PHW) ? w0[v] : 0.f; sx += wx[v]; }

    float acc = 0.f;
#pragma unroll
    for (int u = 0; u < 4; u++) {
        if (wy[u] == 0.f) continue;
        int r = by + u;
        float rowacc = 0.f;
#pragma unroll
        for (int v = 0; v < 4; v++) {
            if (wx[v] == 0.f) continue;
            rowacc += wx[v] * __ldg(&patch[(r * PHW + (bx + v)) * 3 + c]);
        }
        acc += wy[u] * rowacc;
    }
    float val = acc / (sy * sx);
    g_small[t] = val;
    g_smallT[(j * PB + i) * 3 + c] = val;

    __syncthreads();
    __threadfence();
    if (threadIdx.x == 0) atomicAdd(&g_sync[0], 1);
}

// ---------------------------------------------------------------------------
// Role: gradient gather + inverse transform (coalesced for rot and non-rot).
// ---------------------------------------------------------------------------
__device__ void role_gather(int gb, const float* __restrict__ grads,
                            const int* __restrict__ box_yx,
                            const int* __restrict__ dec) {
    __shared__ int s_y[NBG], s_x[NBG], s_d[NBG], s_b[NBG];
    int tid = threadIdx.x;
    int g = gb >> 7;
    int r = gb & 127;

    if (tid < NBG) {
        int box = g * NBG + tid;
        s_y[tid] = __ldg(&box_yx[box * 2]);
        s_x[tid] = __ldg(&box_yx[box * 2 + 1]);
        s_d[tid] = (__ldg(&dec[box * 3]) > 0 ? 1 : 0) |
                   (__ldg(&dec[box * 3 + 1]) > 0 ? 2 : 0) |
                   (__ldg(&dec[box * 3 + 2]) > 0 ? 4 : 0);
        s_b[tid] = box >> 4;
    }
    __syncthreads();

    int j = tid / 3;
    int c = tid - 3 * j;

    float acc_nr = 0.f;
    float acc_rt = 0.f;
#pragma unroll 8
    for (int k = 0; k < NBG; ++k) {
        int d = s_d[k];
        size_t base = (size_t)s_b[k] * (HW * HW * 3);
        if (d & 1) {
            int row = s_y[k] + ((d & 4) ? r : (PB - 1 - r));
            int col = s_x[k] + ((d & 2) ? (PB - 1 - j) : j);
            acc_rt += __ldg(&grads[base + ((size_t)row * HW + col) * 3 + c]);
        } else {
            int row = s_y[k] + ((d & 4) ? (PB - 1 - r) : r);
            int col = s_x[k] + ((d & 2) ? (PB - 1 - j) : j);
            acc_nr += __ldg(&grads[base + ((size_t)row * HW + col) * 3 + c]);
        }
    }
    g_nr[g][r][tid] = acc_nr;
    g_rt[g][r][tid] = acc_rt;

    __syncthreads();
    __threadfence();
    if (tid == 0) atomicAdd(&g_sync[1], 1);
}

// ---------------------------------------------------------------------------
// Role: paste. 4 blocks per box, 32 rows each. Pure stores of the transformed
// tile; later-box-wins via a compacted overlap list (usually empty).
// ---------------------------------------------------------------------------
__device__ void role_paste(int pb_, const int* __restrict__ box_yx,
                           const int* __restrict__ dec,
                           float* __restrict__ out) {
    int box = pb_ >> 2;
    int rbase = (pb_ & 3) * 32;
    int b = box >> 4;
    int n = box & 15;
    int tid = threadIdx.x;

    __shared__ int s_y0, s_x0, s_d;
    __shared__ int l_y[NPER], l_x[NPER];
    __shared__ int l_cnt;

    if (tid == 0) {
        s_y0 = __ldg(&box_yx[box * 2]);
        s_x0 = __ldg(&box_yx[box * 2 + 1]);
        s_d = (__ldg(&dec[box * 3]) > 0 ? 1 : 0) |
              (__ldg(&dec[box * 3 + 1]) > 0 ? 2 : 0) |
              (__ldg(&dec[box * 3 + 2]) > 0 ? 4 : 0);
        l_cnt = 0;
    }
    __syncthreads();

    if (tid >= n + 1 && tid < NPER) {
        int mb = b * NPER + tid;
        int ym = __ldg(&box_yx[mb * 2]);
        int xm = __ldg(&box_yx[mb * 2 + 1]);
        int ylo = s_y0 + rbase, yhi = s_y0 + rbase + 32;
        bool ovl = (ym < yhi) && (ym + PB > ylo) &&
                   (xm < s_x0 + PB) && (xm + PB > s_x0);
        if (ovl) {
            int idx = atomicAdd(&l_cnt, 1);
            l_y[idx] = ym;
            l_x[idx] = xm;
        }
    }

    if (tid == 0) {
        volatile int* p = &g_sync[0];
        while (*p < DS_BLOCKS) __nanosleep(64);
    }
    __syncthreads();

    int rx = tid / 3;
    int c = tid - 3 * rx;
    int d = s_d;
    int x1 = (d & 2) ? (PB - 1 - rx) : rx;
    int xg = s_x0 + rx;
    int cnt = l_cnt;

    for (int r = 0; r < 32; r++) {
        int ry = rbase + r;
        int yg = s_y0 + ry;
        bool skip = false;
        for (int m = 0; m < cnt; m++) {
            if ((unsigned)(yg - l_y[m]) < (unsigned)PB &&
                (unsigned)(xg - l_x[m]) < (unsigned)PB) { skip = true; break; }
        }
        if (skip) continue;
        int y2 = (d & 4) ? (PB - 1 - ry) : ry;
        float val;
        if (d & 1) {
            int sx_ = PB - 1 - y2;
            val = g_smallT[(sx_ * PB + x1) * 3 + c];
        } else {
            val = g_small[(y2 * PB + x1) * 3 + c];
        }
        out[((size_t)(b * HW + yg) * HW + xg) * 3 + c] = val;
    }
}

// ---------------------------------------------------------------------------
// Role: streaming copy, 4 rows/block, coverage-masked stores. Never waits.
// Fully-covered quads skip both the read and the write (paste blocks own them).
// ---------------------------------------------------------------------------
__device__ void role_copy(int cb, const float* __restrict__ images,
                          const int* __restrict__ box_yx,
                          float* __restrict__ out) {
    int b = cb >> 8;                     // 256 blocks per image
    int ybase = (cb & 255) * ROWS_PER_CP;
    int tid = threadIdx.x;

    __shared__ unsigned s_cov[ROWS_PER_CP][32];   // 4 rows x 1024 bits

    for (int w = tid; w < ROWS_PER_CP * 32; w += THREADS)
        ((unsigned*)s_cov)[w] = 0u;
    __syncthreads();

    // build coverage: 64 threads = (box, row)
    if (tid < NPER * ROWS_PER_CP) {
        int bx_ = tid >> 2;              // box 0..15
        int r = tid & 3;                 // row 0..3
        int boxid = b * NPER + bx_;
        int y0 = __ldg(&box_yx[boxid * 2]);
        if ((unsigned)(ybase + r - y0) < (unsigned)PB) {
            int x0 = __ldg(&box_yx[boxid * 2 + 1]);
            int w0 = x0 >> 5, off = x0 & 31;
            if (off == 0) {
#pragma unroll
                for (int w = 0; w < 4; w++) atomicOr(&s_cov[r][w0 + w], 0xFFFFFFFFu);
            } else {
                atomicOr(&s_cov[r][w0], 0xFFFFFFFFu << off);
#pragma unroll
                for (int w = 1; w < 4; w++) atomicOr(&s_cov[r][w0 + w], 0xFFFFFFFFu);
                atomicOr(&s_cov[r][w0 + 4], 0xFFFFFFFFu >> (32 - off));
            }
        }
    }
    __syncthreads();

    size_t base4 = ((size_t)(b * HW + ybase)) * (HW * 3 / 4);
    const float4* src4 = (const float4*)images + base4;
    float4* dst4 = (float4*)out + base4;

#pragma unroll
    for (int h = 0; h < 2; h++) {
        float4 v[4];
        int cc[4];
#pragma unroll
        for (int k = 0; k < 4; k++) {
            int q = h * 4 + k;
            int row = q >> 1;
            int qq = (q & 1) * THREADS + tid;         // float4 idx in row
            int pa = (qq * 4) / 3;                    // first pixel spanned
            int ca = (s_cov[row][pa >> 5] >> (pa & 31)) & 1;
            int cbit = (s_cov[row][(pa + 1) >> 5] >> ((pa + 1) & 31)) & 1;
            cc[k] = ca | (cbit << 1);
            if (cc[k] != 3)
                v[k] = __ldcs(&src4[row * 768 + qq]);
        }
#pragma unroll
        for (int k = 0; k < 4; k++) {
            if (cc[k] == 3) continue;                 // fully pasted
            int q = h * 4 + k;
            int row = q >> 1;
            int qq = (q & 1) * THREADS + tid;
            float4* dp = &dst4[row * 768 + qq];
            if (cc[k] == 0) {
                __stcs(dp, v[k]);
            } else {
                int fo = qq * 4;
                int pa = fo / 3;
                float* df = (float*)dp;
                const float* vf = (const float*)&v[k];
#pragma unroll
                for (int e = 0; e < 4; e++) {
                    int px = (fo + e) / 3;
                    int covered = (px == pa) ? (cc[k] & 1) : ((cc[k] >> 1) & 1);
                    if (!covered) df[e] = vf[e];
                }
            }
        }
    }
}

// ---------------------------------------------------------------------------
// Role: reduce gather partials + bilinear upsample 128->256 + analytic TV grad.
// ---------------------------------------------------------------------------
__device__ __forceinline__ float acc_at(int y, int x, int c) {
    float s = 0.f;
#pragma unroll
    for (int g = 0; g < NGRP; g++) {
        s += g_nr[g][y][x * 3 + c];
        s += g_rt[g][x][y * 3 + c];
    }
    return s;
}

__device__ void role_final(int fb, const float* __restrict__ patch,
                           float* __restrict__ agg) {
    if (threadIdx.x == 0) {
        volatile int* p = &g_sync[1];
        while (*p < GT_BLOCKS) __nanosleep(64);
    }
    __syncthreads();

    int t = fb * THREADS + threadIdx.x;
    int c = t % 3;
    int j = (t / 3) % PHW;
    int i = t / (PHW * 3);

    int ky = i >> 1, y0, y1; float wy0, wy1;
    if (i & 1) { y0 = ky;             y1 = min(ky + 1, PB - 1); wy0 = 0.75f; wy1 = 0.25f; }
    else       { y0 = max(ky - 1, 0); y1 = ky;                  wy0 = 0.25f; wy1 = 0.75f; }
    int kx = j >> 1, x0, x1; float wx0, wx1;
    if (j & 1) { x0 = kx;             x1 = min(kx + 1, PB - 1); wx0 = 0.75f; wx1 = 0.25f; }
    else       { x0 = max(kx - 1, 0); x1 = kx;                  wx0 = 0.25f; wx1 = 0.75f; }

    float v = wy0 * (wx0 * acc_at(y0, x0, c) + wx1 * acc_at(y0, x1, c))
            + wy1 * (wx0 * acc_at(y1, x0, c) + wx1 * acc_at(y1, x1, c));

    float pij = __ldg(&patch[(i * PHW + j) * 3 + c]);
    float a = (j < PHW - 1) ? (pij - __ldg(&patch[(i * PHW + j + 1) * 3 + c])) : 0.f;
    float bb = (i < PHW - 1) ? (pij - __ldg(&patch[((i + 1) * PHW + j) * 3 + c])) : 0.f;
    float g = (a + bb) * rsqrtf(a * a + bb * bb + 1e-12f);
    if (j > 0) {
        float pl = __ldg(&patch[(i * PHW + j - 1) * 3 + c]);
        float al = pl - pij;
        float bl = (i < PHW - 1) ? (pl - __ldg(&patch[((i + 1) * PHW + j - 1) * 3 + c])) : 0.f;
        g -= al * rsqrtf(al * al + bl * bl + 1e-12f);
    }
    if (i > 0) {
        float pu = __ldg(&patch[((i - 1) * PHW + j) * 3 + c]);
        float bu = pu - pij;
        float au = (j < PHW - 1) ? (pu - __ldg(&patch[((i - 1) * PHW + j + 1) * 3 + c])) : 0.f;
        g -= bu * rsqrtf(au * au + bu * bu + 1e-12f);
    }
    agg[t] = v + 0.5f * g;
}

// ---------------------------------------------------------------------------
// Mega kernel, R8 layout (best measured), occupancy target raised to 5 CTAs/SM
// (1920 threads, regs capped at 34).
// ---------------------------------------------------------------------------
__global__ void __launch_bounds__(THREADS, 5) k_mega(
        const float* __restrict__ images, const float* __restrict__ grads,
        const float* __restrict__ patch,
        const int* __restrict__ box_yx, const int* __restrict__ dec,
        float* __restrict__ out, float* __restrict__ agg) {
    int bid = blockIdx.x;
    if (bid < DS_BLOCKS) {
        role_downsample(bid, patch);
    } else if (bid < DS_BLOCKS + GT_BLOCKS) {
        role_gather(bid - DS_BLOCKS, grads, box_yx, dec);
    } else if (bid < DS_BLOCKS + GT_BLOCKS + PS_BLOCKS) {
        role_paste(bid - (DS_BLOCKS + GT_BLOCKS), box_yx, dec, out);
    } else if (bid < DS_BLOCKS + GT_BLOCKS + PS_BLOCKS + CP_BLOCKS) {
        role_copy(bid - (DS_BLOCKS + GT_BLOCKS + PS_BLOCKS), images, box_yx, out);
    } else {
        role_final(bid - (DS_BLOCKS + GT_BLOCKS + PS_BLOCKS + CP_BLOCKS), patch, agg);
    }
}

// ---------------------------------------------------------------------------
extern "C" void kernel_launch(void* const* d_in, const int* in_sizes, int n_in,
                              void* d_out, int out_size) {
    const float* images = (const float*)d_in[0];
    const float* grads  = (const float*)d_in[1];
    const float* patch  = (const float*)d_in[2];
    const int*   box_yx = (const int*)d_in[3];
    const int*   dec    = (const int*)d_in[4];

    float* out = (float*)d_out;
    size_t img_elems = (size_t)BIMG * HW * HW * 3;
    float* agg = out + img_elems;

    void* sptr = nullptr;
    cudaGetSymbolAddress(&sptr, g_sync);
    cudaMemsetAsync(sptr, 0, 2 * sizeof(int));

    k_mega<<<TOTAL_BLOCKS, THREADS>>>(images, grads, patch, box_yx, dec, out, agg);
}